// round 5
// baseline (speedup 1.0000x reference)
#include <cuda_runtime.h>
#include <cuda_bf16.h>
#include <math.h>

// BRITS-style recurrent imputation. B=256, T=512, F=64, H=128, gates=512.
// 64 clusters x 2 CTAs. Cluster owns 4 batch rows; CTA rank r owns h-units
// [r*64, r*64+64) for the gates GEMM + LSTM update; h halves exchanged via
// DSMEM each step. Small weights live in smem; gate weights stream from L2
// k-major (lane-coalesced).
// Output: [loss(1), predictions(256), imputations(256*512*64)].

#define Bsz 256
#define Tt  512
#define Ff  64
#define Hh  128
#define ROWS 4

// ---------------- device-global staging (static, allocation-free) ----------
__device__ __align__(16) float g_W2[2 * 256 * 256]; // [rank][k][out_local]
__device__ float g_bg2[2 * 256];                    // combined gate bias, split
__device__ float g_WdhT[Ff * Hh];                   // [k][hu]
__device__ float g_WhrT[Hh * Ff];                   // [k][f]
__device__ float g_WfrT[Ff * Ff];                   // [k][f], diag zeroed
__device__ float g_WwcT[2 * Ff * Ff];               // [k][f]
__device__ float g_wdx[Ff];
__device__ float g_inv_msum[Tt];
__device__ float g_istrain;
__device__ float g_xloss;
__device__ float g_yloss;

// ---------------- helpers --------------------------------------------------
__device__ __forceinline__ unsigned long long splat2(float w) {
    unsigned long long r; unsigned int wi = __float_as_uint(w);
    asm("mov.b64 %0, {%1, %2};" : "=l"(r) : "r"(wi), "r"(wi));
    return r;
}
__device__ __forceinline__ unsigned long long fma2(unsigned long long a,
                                                   unsigned long long b,
                                                   unsigned long long c) {
    unsigned long long d;
    asm("fma.rn.f32x2 %0, %1, %2, %3;" : "=l"(d) : "l"(a), "l"(b), "l"(c));
    return d;
}
union F2U { unsigned long long u; float2 f; };

__device__ __forceinline__ float sigm(float x) { return 1.f / (1.f + __expf(-x)); }
__device__ __forceinline__ float tanh_e(float x) { return 1.f - 2.f / (__expf(2.f * x) + 1.f); }

__device__ __forceinline__ void st_peer_f32(const void* smem_ptr, unsigned int peer, float v) {
    unsigned int la = (unsigned int)__cvta_generic_to_shared(smem_ptr);
    unsigned int ra;
    asm volatile("mapa.shared::cluster.u32 %0, %1, %2;" : "=r"(ra) : "r"(la), "r"(peer));
    asm volatile("st.shared::cluster.f32 [%0], %1;" :: "r"(ra), "f"(v));
}

// ---------------- prep: transposes + msum + zero accumulators -------------
__global__ void prep_all(const float* __restrict__ masks, const float* __restrict__ is_train,
                         const float* __restrict__ W_dh, const float* __restrict__ W_dx,
                         const float* __restrict__ W_hr, const float* __restrict__ W_fr,
                         const float* __restrict__ W_wc,
                         const float* __restrict__ W_ih, const float* __restrict__ b_ih,
                         const float* __restrict__ W_hh, const float* __restrict__ b_hh) {
    __shared__ float red[256];
    const int bx = blockIdx.x;
    if (bx < Tt) {                       // msum(t)
        float s = 0.f;
        for (int i = threadIdx.x; i < Bsz * Ff; i += 256) {
            int b = i / Ff, f = i % Ff;
            s += masks[(b * Tt + bx) * Ff + f];
        }
        red[threadIdx.x] = s; __syncthreads();
        for (int off = 128; off > 0; off >>= 1) {
            if (threadIdx.x < off) red[threadIdx.x] += red[threadIdx.x + off];
            __syncthreads();
        }
        if (threadIdx.x == 0) g_inv_msum[bx] = 1.f / (red[0] + 1e-5f);
        return;
    }
    if (bx == Tt) {                      // is_train sum + zero losses
        red[threadIdx.x] = is_train[threadIdx.x]; __syncthreads();
        for (int off = 128; off > 0; off >>= 1) {
            if (threadIdx.x < off) red[threadIdx.x] += red[threadIdx.x + off];
            __syncthreads();
        }
        if (threadIdx.x == 0) { g_istrain = red[0]; g_xloss = 0.f; g_yloss = 0.f; }
        return;
    }
    // transposes, grid-stride over the remaining blocks
    const int idx = (bx - Tt - 1) * 256 + threadIdx.x;
    const int stride = 128 * 256;
    for (int i = idx; i < 2 * 256 * 256; i += stride) {
        int r = i >> 16, rem = i & 65535, k = rem >> 8, o = rem & 255;
        int g = o >> 6, u = o & 63;
        int orig = g * 128 + r * 64 + u;
        g_W2[i] = (k < 128) ? W_ih[orig * 128 + k] : W_hh[orig * 128 + (k - 128)];
    }
    for (int i = idx; i < 512; i += stride) {
        int r = i >> 8, o = i & 255, g = o >> 6, u = o & 63;
        int orig = g * 128 + r * 64 + u;
        g_bg2[i] = b_ih[orig] + b_hh[orig];
    }
    for (int i = idx; i < Ff * Hh; i += stride) { int k = i / Hh, o = i % Hh; g_WdhT[i] = W_dh[o * Ff + k]; }
    for (int i = idx; i < Hh * Ff; i += stride) { int k = i / Ff, o = i % Ff; g_WhrT[i] = W_hr[o * Hh + k]; }
    for (int i = idx; i < Ff * Ff; i += stride) { int k = i / Ff, o = i % Ff; g_WfrT[i] = (o == k) ? 0.f : W_fr[o * Ff + k]; }
    for (int i = idx; i < 2 * Ff * Ff; i += stride) { int k = i / Ff, o = i % Ff; g_WwcT[i] = W_wc[o * (2 * Ff) + k]; }
    for (int i = idx; i < Ff; i += stride) g_wdx[i] = W_dx[i * Ff + i];
}

// ---------------- smem layout for main kernel ------------------------------
struct __align__(16) SmemMain {
    float WdhT[Ff * Hh];        // 32KB
    float WhrT[Hh * Ff];        // 32KB
    float WfrT[Ff * Ff];        // 16KB
    float WwcT[2 * Ff * Ff];    // 32KB
    float actT[256 * 4];        // [k][r]: 0-63 c_c, 64-127 m, 128-255 h(decayed)
    float hN[2][Hh * 4];        // raw h double buffer [buf][hu*4+r]
    float cT[Ff * 4];           // my half cell state [u_local*4+r]
    float dT[Ff * 4];
    float gxT[Ff * 4];
    float xcT[Ff * 4];
    float gT[4 * 256];          // gates preact [r][out_local]
    float inv_msum[Tt];
    float b_dh[Hh];
    float b_dx[Ff]; float b_hr[Ff]; float b_fr[Ff]; float b_wc[Ff];
    float wdx[Ff];
    float bg[256];
    float red[256];
};

// ---------------- main persistent scan kernel ------------------------------
__global__ __launch_bounds__(256, 1) __cluster_dims__(2, 1, 1)
void brits_main(const float* __restrict__ values, const float* __restrict__ masks,
                const float* __restrict__ deltas, const float* __restrict__ labels,
                const float* __restrict__ is_train,
                const float* __restrict__ b_dh, const float* __restrict__ b_dx,
                const float* __restrict__ b_hr, const float* __restrict__ b_fr,
                const float* __restrict__ b_wc,
                const float* __restrict__ W_out, const float* __restrict__ b_out,
                float* __restrict__ out) {
    extern __shared__ char smem_raw[];
    SmemMain* s = reinterpret_cast<SmemMain*>(smem_raw);

    unsigned int rank;
    asm("mov.u32 %0, %%cluster_ctarank;" : "=r"(rank));
    const unsigned int peer = rank ^ 1u;

    const int tid = threadIdx.x;
    const int pair = blockIdx.x >> 1;      // cluster id 0..63
    const int b0 = pair * ROWS;
    const int fr_f = tid & 63;             // F-elementwise mapping
    const int fr_r = tid >> 6;
    const int hu = tid & 127;              // full-H mapping
    const int hp = tid >> 7;               // row-pair 0/1

    // ---- init: stage weights into smem ----
    for (int i = tid; i < Ff * Hh; i += 256) s->WdhT[i] = g_WdhT[i];
    for (int i = tid; i < Hh * Ff; i += 256) s->WhrT[i] = g_WhrT[i];
    for (int i = tid; i < Ff * Ff; i += 256) s->WfrT[i] = g_WfrT[i];
    for (int i = tid; i < 2 * Ff * Ff; i += 256) s->WwcT[i] = g_WwcT[i];
    for (int i = tid; i < Tt; i += 256) s->inv_msum[i] = g_inv_msum[i];
    if (tid < Hh) s->b_dh[tid] = b_dh[tid];
    if (tid < Ff) {
        s->b_dx[tid] = b_dx[tid]; s->b_hr[tid] = b_hr[tid];
        s->b_fr[tid] = b_fr[tid]; s->b_wc[tid] = b_wc[tid];
        s->wdx[tid] = g_wdx[tid];
    }
    s->bg[tid] = g_bg2[rank * 256 + tid];
    s->hN[0][hu * 4 + 2 * hp] = 0.f; s->hN[0][hu * 4 + 2 * hp + 1] = 0.f;
    s->hN[1][hu * 4 + 2 * hp] = 0.f; s->hN[1][hu * 4 + 2 * hp + 1] = 0.f;
    if (tid < Ff * 4) s->cT[tid] = 0.f;
    float lacc = 0.f;
    __syncthreads();
    asm volatile("barrier.cluster.arrive.aligned;" ::: "memory");

    const float* wp = g_W2 + (rank << 16) + tid;   // [k][out_local=tid], stride 256
    int gidx = ((b0 + fr_r) * Tt) * Ff + fr_f;

    for (int t = 0; t < Tt; ++t, gidx += Ff) {
        // ---- Stage A: load x,m,d; gamma_x (duplicated across ranks) ------
        const float xv = values[gidx];
        const float mv = masks[gidx];
        const float dv = deltas[gidx];
        s->actT[(64 + fr_f) * 4 + fr_r] = mv;
        s->dT[fr_f * 4 + fr_r] = dv;
        s->gxT[fr_f * 4 + fr_r] = __expf(-fmaxf(dv * s->wdx[fr_f] + s->b_dx[fr_f], 0.f));
        __syncthreads();
        asm volatile("barrier.cluster.wait.aligned;" ::: "memory");

        // ---- Stage B: gamma_h + decay full h (duplicated) ----------------
        {
            float a0 = 0.f, a1 = 0.f;
#pragma unroll 8
            for (int k = 0; k < Ff; ++k) {
                const float w = s->WdhT[k * Hh + hu];
                const float2 dp = *reinterpret_cast<const float2*>(&s->dT[k * 4 + 2 * hp]);
                a0 += w * dp.x;
                a1 += w * dp.y;
            }
            const float bb = s->b_dh[hu];
            const float g0 = __expf(-fmaxf(a0 + bb, 0.f));
            const float g1 = __expf(-fmaxf(a1 + bb, 0.f));
            const float* hsrc = s->hN[(t + 1) & 1];
            s->actT[(128 + hu) * 4 + 2 * hp]     = hsrc[hu * 4 + 2 * hp] * g0;
            s->actT[(128 + hu) * 4 + 2 * hp + 1] = hsrc[hu * 4 + 2 * hp + 1] * g1;
        }
        __syncthreads();

        // ---- Stage E1: gates GEMM, k=64..255 (m + decayed h) -------------
        unsigned long long acc0 = 0ull, acc1 = 0ull;   // rows (0,1) and (2,3)
        {
#pragma unroll 8
            for (int k = 64; k < 256; ++k) {
                const float w = wp[k << 8];
                const ulonglong2 av = *reinterpret_cast<const ulonglong2*>(&s->actT[k * 4]);
                const unsigned long long w2 = splat2(w);
                acc0 = fma2(w2, av.x, acc0);
                acc1 = fma2(w2, av.y, acc1);
            }
        }
        // ---- Stage C (same phase): x_h -----------------------------------
        float x_h;
        {
            float acc = 0.f;
#pragma unroll 8
            for (int k = 0; k < Hh; ++k)
                acc += s->WhrT[k * Ff + fr_f] * s->actT[(128 + k) * 4 + fr_r];
            x_h = acc + s->b_hr[fr_f];
        }
        const float l1 = fabsf(xv - x_h) * mv;
        const float x_c = mv * xv + (1.f - mv) * x_h;
        s->xcT[fr_f * 4 + fr_r] = x_c;
        __syncthreads();

        // ---- Stage D: z_h, alpha, c_h, c_c, losses -----------------------
        {
            float za = 0.f;
#pragma unroll 8
            for (int k = 0; k < Ff; ++k)
                za += s->WfrT[k * Ff + fr_f] * s->xcT[k * 4 + fr_r];
            const float z_h = za + s->b_fr[fr_f];
            float aa = 0.f;
#pragma unroll 8
            for (int k = 0; k < Ff; ++k)
                aa += s->WwcT[k * Ff + fr_f] * s->gxT[k * 4 + fr_r];
#pragma unroll 8
            for (int k = 0; k < Ff; ++k)
                aa += s->WwcT[(64 + k) * Ff + fr_f] * s->actT[(64 + k) * 4 + fr_r];
            const float alpha = aa + s->b_wc[fr_f];
            const float c_h = alpha * z_h + (1.f - alpha) * x_h;
            const float l2 = fabsf(xv - z_h) * mv;
            const float l3 = fabsf(xv - c_h) * mv;
            lacc += (l1 + l2 + l3) * s->inv_msum[t];
            const float c_c = mv * xv + (1.f - mv) * c_h;
            if (rank == 0) out[1 + Bsz + gidx] = c_c;   // imputations
            s->actT[fr_f * 4 + fr_r] = c_c;
        }
        __syncthreads();

        // ---- Stage E2: gates GEMM, k=0..63 (c_c); write gT ---------------
        {
#pragma unroll 8
            for (int k = 0; k < 64; ++k) {
                const float w = wp[k << 8];
                const ulonglong2 av = *reinterpret_cast<const ulonglong2*>(&s->actT[k * 4]);
                const unsigned long long w2 = splat2(w);
                acc0 = fma2(w2, av.x, acc0);
                acc1 = fma2(w2, av.y, acc1);
            }
            F2U u0, u1; u0.u = acc0; u1.u = acc1;
            const float bgv = s->bg[tid];
            s->gT[0 * 256 + tid] = u0.f.x + bgv;
            s->gT[1 * 256 + tid] = u0.f.y + bgv;
            s->gT[2 * 256 + tid] = u1.f.x + bgv;
            s->gT[3 * 256 + tid] = u1.f.y + bgv;
        }
        __syncthreads();

        // ---- Stage F: LSTM update on my 64 units, exchange h -------------
        {
            const int u = tid & 63;
            const int r = tid >> 6;
            const float ig = s->gT[r * 256 + u];
            const float fg = s->gT[r * 256 + 64 + u];
            const float gg = s->gT[r * 256 + 128 + u];
            const float og = s->gT[r * 256 + 192 + u];
            const float cn = sigm(fg) * s->cT[u * 4 + r] + sigm(ig) * tanh_e(gg);
            s->cT[u * 4 + r] = cn;
            const float hn = sigm(og) * tanh_e(cn);
            const int gu = rank * 64 + u;
            float* dst = &s->hN[t & 1][gu * 4 + r];
            *dst = hn;
            st_peer_f32(dst, peer, hn);
        }
        asm volatile("barrier.cluster.arrive.aligned;" ::: "memory");
    }

    asm volatile("barrier.cluster.wait.aligned;" ::: "memory");
    __syncthreads();

    if (rank == 0) {
        // ---- x_loss block reduce ----
        s->red[tid] = lacc; __syncthreads();
        for (int off = 128; off > 0; off >>= 1) {
            if (tid < off) s->red[tid] += s->red[tid + off];
            __syncthreads();
        }
        if (tid == 0) atomicAdd(&g_xloss, s->red[0]);

        // ---- y head: warp w handles row w ----
        const int wid = tid >> 5, lid = tid & 31;
        if (wid < ROWS) {
            const float* hfin = s->hN[(Tt - 1) & 1];
            float acc = 0.f;
#pragma unroll
            for (int u = lid; u < Hh; u += 32)
                acc += hfin[u * 4 + wid] * W_out[u];
#pragma unroll
            for (int off = 16; off > 0; off >>= 1)
                acc += __shfl_down_sync(0xffffffffu, acc, off);
            if (lid == 0) {
                const int b = b0 + wid;
                const float yh = acc + b_out[0];
                out[1 + b] = 1.f / (1.f + expf(-yh));
                const float lab = labels[b];
                const float mx = fmaxf(-yh, 0.f);
                const float yl = yh - yh * lab + mx + logf(expf(-mx) + expf(-yh - mx));
                atomicAdd(&g_yloss, yl * is_train[b]);
            }
        }
    }
}

// ---------------- finalize --------------------------------------------------
__global__ void finalize_loss(float* __restrict__ out) {
    out[0] = g_xloss * (1.f / (float)Tt) + 0.3f * (g_yloss / (g_istrain + 1e-5f));
}

// ---------------- launch ----------------------------------------------------
extern "C" void kernel_launch(void* const* d_in, const int* in_sizes, int n_in,
                              void* d_out, int out_size) {
    (void)in_sizes; (void)n_in; (void)out_size;
    const float* values   = (const float*)d_in[0];
    const float* masks    = (const float*)d_in[1];
    const float* deltas   = (const float*)d_in[2];
    const float* labels   = (const float*)d_in[3];
    const float* is_train = (const float*)d_in[4];
    const float* W_dh = (const float*)d_in[5];
    const float* b_dh = (const float*)d_in[6];
    const float* W_dx = (const float*)d_in[7];
    const float* b_dx = (const float*)d_in[8];
    const float* W_hr = (const float*)d_in[9];
    const float* b_hr = (const float*)d_in[10];
    const float* W_fr = (const float*)d_in[11];
    const float* b_fr = (const float*)d_in[12];
    const float* W_wc = (const float*)d_in[13];
    const float* b_wc = (const float*)d_in[14];
    const float* W_ih = (const float*)d_in[15];
    const float* b_ih = (const float*)d_in[16];
    const float* W_hh = (const float*)d_in[17];
    const float* b_hh = (const float*)d_in[18];
    const float* W_out = (const float*)d_in[19];
    const float* b_out = (const float*)d_in[20];
    float* out = (float*)d_out;

    static const size_t smem_bytes = sizeof(SmemMain);
    cudaFuncSetAttribute(brits_main, cudaFuncAttributeMaxDynamicSharedMemorySize,
                         (int)smem_bytes);

    prep_all<<<Tt + 1 + 128, 256>>>(masks, is_train, W_dh, W_dx, W_hr, W_fr, W_wc,
                                    W_ih, b_ih, W_hh, b_hh);
    brits_main<<<128, 256, smem_bytes>>>(values, masks, deltas, labels, is_train,
                                         b_dh, b_dx, b_hr, b_fr, b_wc, W_out, b_out, out);
    finalize_loss<<<1, 1>>>(out);
}